// round 2
// baseline (speedup 1.0000x reference)
#include <cuda_runtime.h>
#include <cstdint>

#define MAXN 50000
#define MAXE 800000
#define FIN 256
#define FH  64
#define FOUT 40
#define KSTEPS 10

// ---------------- static device scratch (no allocations allowed) ----------------
__device__ int   g_deg[MAXN];                       // degree incl. self loop
__device__ float g_dinv[MAXN];                      // deg^-1/2
__device__ int   g_ptr[MAXN + 1];                   // CSR (by destination) pointers
__device__ int   g_cursor[MAXN];                    // scatter cursors
__device__ __align__(16) int2  g_csr[MAXE];         // {src, weight bits} grouped by dst
__device__ __align__(16) float g_h0[MAXN * FH];     // teleport target
__device__ __align__(16) float g_hA[MAXN * FH];     // ping
__device__ __align__(16) float g_hB[MAXN * FH];     // pong (also MLP1 intermediate)

__device__ __forceinline__ int clampN(int v, int n) {
    v = v < 0 ? 0 : v;
    return v >= n ? n - 1 : v;
}

// ---------------- graph preprocessing ----------------
__global__ void init_kernel(int n) {
    int i = blockIdx.x * blockDim.x + threadIdx.x;
    if (i < n) { g_deg[i] = 1; g_cursor[i] = 0; }   // self loop counts 1
}

__global__ void hist_kernel(const int* __restrict__ ei, int E, int n) {
    int e = blockIdx.x * blockDim.x + threadIdx.x;
    if (e < E) {
        int c = clampN(ei[E + e], n);               // col = target
        atomicAdd(&g_deg[c], 1);
    }
}

__global__ void dinv_kernel(int n) {
    int i = blockIdx.x * blockDim.x + threadIdx.x;
    if (i < n) g_dinv[i] = rsqrtf((float)g_deg[i]);
}

// single-block exclusive scan of (deg[i]-1) -> g_ptr
__global__ void scan_kernel(int n) {
    __shared__ int warp_sums[32];
    __shared__ int s_carry;
    int tid = threadIdx.x, lane = tid & 31, wid = tid >> 5;
    int nwarps = blockDim.x >> 5;
    if (tid == 0) s_carry = 0;
    __syncthreads();
    for (int base = 0; base < n; base += blockDim.x) {
        int i = base + tid;
        int v = (i < n) ? (g_deg[i] - 1) : 0;
        int x = v;
        #pragma unroll
        for (int o = 1; o < 32; o <<= 1) {
            int y = __shfl_up_sync(0xFFFFFFFFu, x, o);
            if (lane >= o) x += y;
        }
        if (lane == 31) warp_sums[wid] = x;
        __syncthreads();
        if (wid == 0) {
            int s = (lane < nwarps) ? warp_sums[lane] : 0;
            #pragma unroll
            for (int o = 1; o < 32; o <<= 1) {
                int y = __shfl_up_sync(0xFFFFFFFFu, s, o);
                if (lane >= o) s += y;
            }
            warp_sums[lane] = s;
        }
        __syncthreads();
        int incl = x + (wid > 0 ? warp_sums[wid - 1] : 0) + s_carry;
        if (i < n) g_ptr[i] = incl - v;             // exclusive
        __syncthreads();
        if (tid == blockDim.x - 1) s_carry = incl;
        __syncthreads();
    }
    if (tid == 0) g_ptr[n] = s_carry;
}

__global__ void scatter_kernel(const int* __restrict__ ei, int E, int n) {
    int e = blockIdx.x * blockDim.x + threadIdx.x;
    if (e < E) {
        int r = clampN(ei[e], n);
        int c = clampN(ei[E + e], n);
        int pos = g_ptr[c] + atomicAdd(&g_cursor[c], 1);
        float w = g_dinv[r] * g_dinv[c];
        g_csr[pos] = make_int2(r, __float_as_int(w));
    }
}

// ---------------- MLP encode (warp per node, shuffle GEMM) ----------------
__global__ void mlp1_kernel(const float* __restrict__ x,
                            const float* __restrict__ W1,
                            const float* __restrict__ b1, int n) {
    int warp = (blockIdx.x * blockDim.x + threadIdx.x) >> 5;
    int lane = threadIdx.x & 31;
    if (warp >= n) return;
    const float* xr = x + (size_t)warp * FIN;
    float acc0 = b1[lane], acc1 = b1[lane + 32];
    for (int kb = 0; kb < FIN; kb += 32) {
        float xv = xr[kb + lane];
        #pragma unroll
        for (int j = 0; j < 32; j++) {
            float xk = __shfl_sync(0xFFFFFFFFu, xv, j);
            int k = kb + j;
            acc0 = fmaf(xk, W1[k * FH + lane],      acc0);
            acc1 = fmaf(xk, W1[k * FH + lane + 32], acc1);
        }
    }
    g_hB[warp * FH + lane]      = fmaxf(acc0, 0.0f);
    g_hB[warp * FH + lane + 32] = fmaxf(acc1, 0.0f);
}

__global__ void mlp2_kernel(const float* __restrict__ W2,
                            const float* __restrict__ b2, int n) {
    int warp = (blockIdx.x * blockDim.x + threadIdx.x) >> 5;
    int lane = threadIdx.x & 31;
    if (warp >= n) return;
    const float* hr = g_hB + warp * FH;
    float acc0 = b2[lane], acc1 = b2[lane + 32];
    for (int kb = 0; kb < FH; kb += 32) {
        float hv = hr[kb + lane];
        #pragma unroll
        for (int j = 0; j < 32; j++) {
            float hk = __shfl_sync(0xFFFFFFFFu, hv, j);
            int k = kb + j;
            acc0 = fmaf(hk, W2[k * FH + lane],      acc0);
            acc1 = fmaf(hk, W2[k * FH + lane + 32], acc1);
        }
    }
    g_hA[warp * FH + lane]      = acc0;
    g_hA[warp * FH + lane + 32] = acc1;
    g_h0[warp * FH + lane]      = acc0;
    g_h0[warp * FH + lane + 32] = acc1;
}

// ---------------- APPNP propagation step (gather-CSR, warp per node) ----------------
__global__ void prop_kernel(int src_is_A, int n) {
    int node = (blockIdx.x * blockDim.x + threadIdx.x) >> 5;
    int lane = threadIdx.x & 31;
    if (node >= n) return;
    const float2* hin2 = src_is_A ? (const float2*)g_hA : (const float2*)g_hB;
    float2*       hout = src_is_A ? (float2*)g_hB : (float2*)g_hA;

    int start = g_ptr[node];
    int end   = g_ptr[node + 1];

    float di = g_dinv[node];
    float wself = di * di;
    float2 hv = hin2[node * 32 + lane];
    float ax = wself * hv.x;
    float ay = wself * hv.y;

    for (int base = start; base < end; base += 32) {
        int e = base + lane;
        int2 sw = (e < end) ? g_csr[e] : make_int2(0, 0);
        int cnt = min(32, end - base);
        for (int j = 0; j < cnt; j++) {
            int   ss = __shfl_sync(0xFFFFFFFFu, sw.x, j);
            float ww = __int_as_float(__shfl_sync(0xFFFFFFFFu, sw.y, j));
            float2 v = hin2[ss * 32 + lane];
            ax = fmaf(ww, v.x, ax);
            ay = fmaf(ww, v.y, ay);
        }
    }
    const float2* h02 = (const float2*)g_h0;
    float2 t = h02[node * 32 + lane];
    float2 o;
    o.x = 0.9f * ax + 0.1f * t.x;
    o.y = 0.9f * ay + 0.1f * t.y;
    hout[node * 32 + lane] = o;
}

// ---------------- decode: out = h @ Wf + bf ----------------
__global__ void decode_kernel(const float* __restrict__ Wf,
                              const float* __restrict__ bf,
                              float* __restrict__ out, int n) {
    int warp = (blockIdx.x * blockDim.x + threadIdx.x) >> 5;
    int lane = threadIdx.x & 31;
    if (warp >= n) return;
    const float* hr = g_hA + warp * FH;    // final buffer after 10 steps
    float acc0 = bf[lane];                 // lanes 0..31 -> cols 0..31
    float acc1 = (lane < FOUT - 32) ? bf[lane + 32] : 0.0f;
    for (int kb = 0; kb < FH; kb += 32) {
        float hv = hr[kb + lane];
        #pragma unroll
        for (int j = 0; j < 32; j++) {
            float hk = __shfl_sync(0xFFFFFFFFu, hv, j);
            int k = kb + j;
            acc0 = fmaf(hk, Wf[k * FOUT + lane], acc0);
            if (lane < FOUT - 32)
                acc1 = fmaf(hk, Wf[k * FOUT + lane + 32], acc1);
        }
    }
    out[(size_t)warp * FOUT + lane] = acc0;
    if (lane < FOUT - 32)
        out[(size_t)warp * FOUT + lane + 32] = acc1;
}

// ---------------- launch ----------------
extern "C" void kernel_launch(void* const* d_in, const int* in_sizes, int n_in,
                              void* d_out, int out_size) {
    const float* x  = (const float*)d_in[0];
    const int*   ei = (const int*)d_in[1];   // JAX x64 disabled -> int32 edge_index
    const float* W1 = (const float*)d_in[2];
    const float* b1 = (const float*)d_in[3];
    const float* W2 = (const float*)d_in[4];
    const float* b2 = (const float*)d_in[5];
    const float* Wf = (const float*)d_in[6];
    const float* bf = (const float*)d_in[7];

    int N = in_sizes[0] / FIN;
    int E = in_sizes[1] / 2;
    if (N > MAXN) N = MAXN;
    if (E > MAXE) E = MAXE;

    int tpb = 256;
    // graph preprocessing
    init_kernel<<<(N + tpb - 1) / tpb, tpb>>>(N);
    hist_kernel<<<(E + tpb - 1) / tpb, tpb>>>(ei, E, N);
    dinv_kernel<<<(N + tpb - 1) / tpb, tpb>>>(N);
    scan_kernel<<<1, 1024>>>(N);
    scatter_kernel<<<(E + tpb - 1) / tpb, tpb>>>(ei, E, N);

    // MLP encode
    int wblocks = (N + 7) / 8;                // 8 warps per 256-thread block
    mlp1_kernel<<<wblocks, tpb>>>(x, W1, b1, N);
    mlp2_kernel<<<wblocks, tpb>>>(W2, b2, N);

    // 10 APPNP steps, ping-pong A<->B ; step t even reads A
    for (int t = 0; t < KSTEPS; t++) {
        prop_kernel<<<wblocks, tpb>>>((t & 1) == 0 ? 1 : 0, N);
    }
    // after 10 steps (even count) result is back in g_hA
    decode_kernel<<<wblocks, tpb>>>(Wf, bf, (float*)d_out, N);
}

// round 3
// speedup vs baseline: 1.1052x; 1.1052x over previous
#include <cuda_runtime.h>
#include <cuda_fp16.h>
#include <cstdint>

#define MAXN 50000
#define MAXE 800000
#define FIN 256
#define FH  64
#define FOUT 40
#define KSTEPS 10
#define SCAN_TPB 256
#define MAXBLK 256          // ceil(MAXN/SCAN_TPB) = 196 <= 256

// ---------------- static device scratch ----------------
__device__ int     g_deg[MAXN];
__device__ float   g_dinv[MAXN];
__device__ int     g_ptr[MAXN + 1];
__device__ int     g_cursor[MAXN];
__device__ int     g_part[MAXBLK];
__device__ __align__(16) int2    g_csr[MAXE];
// h layout: half2 slot p of node holds features (p, p+32); h0 float2 same pairing
__device__ __align__(16) float2  g_h0[MAXN * 32];
__device__ __align__(16) __half2 g_hA[MAXN * 32];
__device__ __align__(16) __half2 g_hB[MAXN * 32];
__device__ __align__(16) float   g_mlp1[MAXN * FH];   // ReLU intermediate (fp32)

__device__ __forceinline__ int clampN(int v, int n) {
    v = v < 0 ? 0 : v;
    return v >= n ? n - 1 : v;
}

// ---------------- graph preprocessing ----------------
__global__ void init_kernel(int n) {
    int i = blockIdx.x * blockDim.x + threadIdx.x;
    if (i < n) { g_deg[i] = 1; g_cursor[i] = 0; }   // self loop
}

__global__ void hist_kernel(const int* __restrict__ ei, int E, int n) {
    int e = blockIdx.x * blockDim.x + threadIdx.x;
    if (e < E) atomicAdd(&g_deg[clampN(ei[E + e], n)], 1);
}

__global__ void dinv_kernel(int n) {
    int i = blockIdx.x * blockDim.x + threadIdx.x;
    if (i < n) g_dinv[i] = rsqrtf((float)g_deg[i]);
}

// scan stage A: per-block sums of (deg-1)
__global__ void scanA_kernel(int n) {
    int i = blockIdx.x * blockDim.x + threadIdx.x;
    int lane = threadIdx.x & 31, wid = threadIdx.x >> 5;
    __shared__ int ws[SCAN_TPB / 32];
    int v = (i < n) ? (g_deg[i] - 1) : 0;
    #pragma unroll
    for (int o = 16; o > 0; o >>= 1) v += __shfl_down_sync(0xFFFFFFFFu, v, o);
    if (lane == 0) ws[wid] = v;
    __syncthreads();
    if (wid == 0) {
        int s = (lane < SCAN_TPB / 32) ? ws[lane] : 0;
        #pragma unroll
        for (int o = 16; o > 0; o >>= 1) s += __shfl_down_sync(0xFFFFFFFFu, s, o);
        if (lane == 0) g_part[blockIdx.x] = s;
    }
}

// scan stage B: exclusive scan of block partials (single block), writes g_ptr[n]
__global__ void scanB_kernel(int nblocks, int n) {
    int tid = threadIdx.x, lane = tid & 31, wid = tid >> 5;
    __shared__ int ws[8];
    int v = (tid < nblocks) ? g_part[tid] : 0;
    int x = v;
    #pragma unroll
    for (int o = 1; o < 32; o <<= 1) {
        int y = __shfl_up_sync(0xFFFFFFFFu, x, o);
        if (lane >= o) x += y;
    }
    if (lane == 31) ws[wid] = x;
    __syncthreads();
    if (wid == 0) {
        int s = (lane < 8) ? ws[lane] : 0;
        #pragma unroll
        for (int o = 1; o < 8; o <<= 1) {
            int y = __shfl_up_sync(0xFFFFFFFFu, s, o);
            if (lane >= o) s += y;
        }
        ws[lane] = s;
    }
    __syncthreads();
    int incl = x + (wid > 0 ? ws[wid - 1] : 0);
    if (tid < nblocks) g_part[tid] = incl - v;       // exclusive
    if (tid == nblocks - 1) g_ptr[n] = incl;         // total
}

// scan stage C: intra-block exclusive scan + block offset -> g_ptr
__global__ void scanC_kernel(int n) {
    int i = blockIdx.x * blockDim.x + threadIdx.x;
    int lane = threadIdx.x & 31, wid = threadIdx.x >> 5;
    __shared__ int ws[SCAN_TPB / 32];
    int v = (i < n) ? (g_deg[i] - 1) : 0;
    int x = v;
    #pragma unroll
    for (int o = 1; o < 32; o <<= 1) {
        int y = __shfl_up_sync(0xFFFFFFFFu, x, o);
        if (lane >= o) x += y;
    }
    if (lane == 31) ws[wid] = x;
    __syncthreads();
    if (wid == 0) {
        int s = (lane < SCAN_TPB / 32) ? ws[lane] : 0;
        #pragma unroll
        for (int o = 1; o < SCAN_TPB / 32; o <<= 1) {
            int y = __shfl_up_sync(0xFFFFFFFFu, s, o);
            if (lane >= o) s += y;
        }
        ws[lane] = s;
    }
    __syncthreads();
    int incl = x + (wid > 0 ? ws[wid - 1] : 0);
    if (i < n) g_ptr[i] = incl - v + g_part[blockIdx.x];
}

__global__ void scatter_kernel(const int* __restrict__ ei, int E, int n) {
    int e = blockIdx.x * blockDim.x + threadIdx.x;
    if (e < E) {
        int r = clampN(ei[e], n);
        int c = clampN(ei[E + e], n);
        int pos = g_ptr[c] + atomicAdd(&g_cursor[c], 1);
        float w = g_dinv[r] * g_dinv[c];
        g_csr[pos] = make_int2(r, __float_as_int(w));
    }
}

// ---------------- MLP encode (warp per node, shuffle GEMM) ----------------
__global__ void mlp1_kernel(const float* __restrict__ x,
                            const float* __restrict__ W1,
                            const float* __restrict__ b1, int n) {
    int warp = (blockIdx.x * blockDim.x + threadIdx.x) >> 5;
    int lane = threadIdx.x & 31;
    if (warp >= n) return;
    const float* xr = x + (size_t)warp * FIN;
    float acc0 = b1[lane], acc1 = b1[lane + 32];
    for (int kb = 0; kb < FIN; kb += 32) {
        float xv = xr[kb + lane];
        #pragma unroll
        for (int j = 0; j < 32; j++) {
            float xk = __shfl_sync(0xFFFFFFFFu, xv, j);
            int k = kb + j;
            acc0 = fmaf(xk, W1[k * FH + lane],      acc0);
            acc1 = fmaf(xk, W1[k * FH + lane + 32], acc1);
        }
    }
    g_mlp1[warp * FH + lane]      = fmaxf(acc0, 0.0f);
    g_mlp1[warp * FH + lane + 32] = fmaxf(acc1, 0.0f);
}

__global__ void mlp2_kernel(const float* __restrict__ W2,
                            const float* __restrict__ b2, int n) {
    int warp = (blockIdx.x * blockDim.x + threadIdx.x) >> 5;
    int lane = threadIdx.x & 31;
    if (warp >= n) return;
    const float* hr = g_mlp1 + warp * FH;
    float acc0 = b2[lane], acc1 = b2[lane + 32];
    for (int kb = 0; kb < FH; kb += 32) {
        float hv = hr[kb + lane];
        #pragma unroll
        for (int j = 0; j < 32; j++) {
            float hk = __shfl_sync(0xFFFFFFFFu, hv, j);
            int k = kb + j;
            acc0 = fmaf(hk, W2[k * FH + lane],      acc0);
            acc1 = fmaf(hk, W2[k * FH + lane + 32], acc1);
        }
    }
    // half2 slot lane holds features (lane, lane+32)
    g_hA[warp * 32 + lane] = __floats2half2_rn(acc0, acc1);
    g_h0[warp * 32 + lane] = make_float2(acc0, acc1);
}

// ---------------- APPNP step: gather-CSR, warp/node, fp16 storage fp32 accum ----
template <int SRC_A>
__global__ void prop_kernel(int n) {
    int node = (blockIdx.x * blockDim.x + threadIdx.x) >> 5;
    int lane = threadIdx.x & 31;
    if (node >= n) return;
    const __half2* __restrict__ hin  = SRC_A ? g_hA : g_hB;
    __half2*       __restrict__ hout = SRC_A ? g_hB : g_hA;

    int start = g_ptr[node];
    int end   = g_ptr[node + 1];

    float di = g_dinv[node];
    float wself = di * di;
    float2 hv = __half22float2(hin[node * 32 + lane]);
    float ax = wself * hv.x;
    float ay = wself * hv.y;

    for (int base = start; base < end; base += 32) {
        int e = base + lane;
        int2 sw = (e < end) ? g_csr[e] : make_int2(0, 0);
        int cnt = min(32, end - base);
        for (int j = 0; j < cnt; j++) {
            int   ss = __shfl_sync(0xFFFFFFFFu, sw.x, j);
            float ww = __int_as_float(__shfl_sync(0xFFFFFFFFu, sw.y, j));
            float2 v = __half22float2(hin[ss * 32 + lane]);
            ax = fmaf(ww, v.x, ax);
            ay = fmaf(ww, v.y, ay);
        }
    }
    float2 t = g_h0[node * 32 + lane];
    hout[node * 32 + lane] =
        __floats2half2_rn(0.9f * ax + 0.1f * t.x, 0.9f * ay + 0.1f * t.y);
}

// ---------------- decode: out = h @ Wf + bf ----------------
__global__ void decode_kernel(const float* __restrict__ Wf,
                              const float* __restrict__ bf,
                              float* __restrict__ out, int n) {
    int warp = (blockIdx.x * blockDim.x + threadIdx.x) >> 5;
    int lane = threadIdx.x & 31;
    if (warp >= n) return;
    float2 hf = __half22float2(g_hA[warp * 32 + lane]);  // (feat lane, feat lane+32)
    float acc0 = bf[lane];
    float acc1 = (lane < FOUT - 32) ? bf[lane + 32] : 0.0f;
    #pragma unroll
    for (int half = 0; half < 2; half++) {
        float hv = half == 0 ? hf.x : hf.y;
        #pragma unroll
        for (int j = 0; j < 32; j++) {
            float hk = __shfl_sync(0xFFFFFFFFu, hv, j);
            int k = half * 32 + j;
            acc0 = fmaf(hk, Wf[k * FOUT + lane], acc0);
            if (lane < FOUT - 32)
                acc1 = fmaf(hk, Wf[k * FOUT + lane + 32], acc1);
        }
    }
    out[(size_t)warp * FOUT + lane] = acc0;
    if (lane < FOUT - 32)
        out[(size_t)warp * FOUT + lane + 32] = acc1;
}

// ---------------- launch ----------------
extern "C" void kernel_launch(void* const* d_in, const int* in_sizes, int n_in,
                              void* d_out, int out_size) {
    const float* x  = (const float*)d_in[0];
    const int*   ei = (const int*)d_in[1];
    const float* W1 = (const float*)d_in[2];
    const float* b1 = (const float*)d_in[3];
    const float* W2 = (const float*)d_in[4];
    const float* b2 = (const float*)d_in[5];
    const float* Wf = (const float*)d_in[6];
    const float* bf = (const float*)d_in[7];

    int N = in_sizes[0] / FIN;
    int E = in_sizes[1] / 2;
    if (N > MAXN) N = MAXN;
    if (E > MAXE) E = MAXE;

    int tpb = 256;
    int nblk = (N + SCAN_TPB - 1) / SCAN_TPB;

    init_kernel<<<(N + tpb - 1) / tpb, tpb>>>(N);
    hist_kernel<<<(E + tpb - 1) / tpb, tpb>>>(ei, E, N);
    dinv_kernel<<<(N + tpb - 1) / tpb, tpb>>>(N);
    scanA_kernel<<<nblk, SCAN_TPB>>>(N);
    scanB_kernel<<<1, MAXBLK>>>(nblk, N);
    scanC_kernel<<<nblk, SCAN_TPB>>>(N);
    scatter_kernel<<<(E + tpb - 1) / tpb, tpb>>>(ei, E, N);

    int wblocks = (N + 7) / 8;                 // 8 warps / 256-thread block
    mlp1_kernel<<<wblocks, tpb>>>(x, W1, b1, N);
    mlp2_kernel<<<wblocks, tpb>>>(W2, b2, N);

    for (int t = 0; t < KSTEPS; t++) {
        if ((t & 1) == 0) prop_kernel<1><<<wblocks, tpb>>>(N);
        else              prop_kernel<0><<<wblocks, tpb>>>(N);
    }
    decode_kernel<<<wblocks, tpb>>>(Wf, bf, (float*)d_out, N);
}

// round 4
// speedup vs baseline: 1.1798x; 1.0674x over previous
#include <cuda_runtime.h>
#include <cuda_fp16.h>
#include <cstdint>

#define MAXN 50000
#define MAXE 800000
#define FIN 256
#define FH  64
#define FOUT 40
#define KSTEPS 10
#define SCAN_TPB 256
#define MAXBLK 256          // ceil(MAXN/SCAN_TPB) = 196 <= 256

// packed fp32x2 helpers (Blackwell dual-issue fp32)
#define PACK2(out, lo, hi) asm("mov.b64 %0, {%1, %2};" : "=l"(out) : "f"(lo), "f"(hi))
#define UNPACK2(lo, hi, in) asm("mov.b64 {%0, %1}, %2;" : "=f"(lo), "=f"(hi) : "l"(in))
#define FMA2(d, a, b, c) asm("fma.rn.f32x2 %0, %1, %2, %3;" : "=l"(d) : "l"(a), "l"(b), "l"(c))

// ---------------- static device scratch ----------------
__device__ int     g_deg[MAXN];
__device__ float   g_dinv[MAXN];
__device__ int     g_ptr[MAXN + 1];
__device__ int     g_cursor[MAXN];
__device__ int     g_part[MAXBLK];
__device__ __align__(16) int2    g_csr[MAXE];
// feature pairing: slot p of a node = features (2p, 2p+1)
__device__ __align__(16) float2  g_h0[MAXN * 32];
__device__ __align__(16) __half2 g_hA[MAXN * 32];
__device__ __align__(16) __half2 g_hB[MAXN * 32];
__device__ __align__(16) float   g_mlp1[MAXN * FH];   // ReLU intermediate (fp32)

__device__ __forceinline__ int clampN(int v, int n) {
    v = v < 0 ? 0 : v;
    return v >= n ? n - 1 : v;
}

// ---------------- graph preprocessing ----------------
__global__ void init_kernel(int n) {
    int i = blockIdx.x * blockDim.x + threadIdx.x;
    if (i < n) { g_deg[i] = 1; g_cursor[i] = 0; }   // self loop
}

__global__ void hist_kernel(const int* __restrict__ ei, int E, int n) {
    int e = blockIdx.x * blockDim.x + threadIdx.x;
    if (e < E) atomicAdd(&g_deg[clampN(ei[E + e], n)], 1);
}

__global__ void dinv_kernel(int n) {
    int i = blockIdx.x * blockDim.x + threadIdx.x;
    if (i < n) g_dinv[i] = rsqrtf((float)g_deg[i]);
}

// scan stage A: per-block sums of (deg-1)
__global__ void scanA_kernel(int n) {
    int i = blockIdx.x * blockDim.x + threadIdx.x;
    int lane = threadIdx.x & 31, wid = threadIdx.x >> 5;
    __shared__ int ws[SCAN_TPB / 32];
    int v = (i < n) ? (g_deg[i] - 1) : 0;
    #pragma unroll
    for (int o = 16; o > 0; o >>= 1) v += __shfl_down_sync(0xFFFFFFFFu, v, o);
    if (lane == 0) ws[wid] = v;
    __syncthreads();
    if (wid == 0) {
        int s = (lane < SCAN_TPB / 32) ? ws[lane] : 0;
        #pragma unroll
        for (int o = 16; o > 0; o >>= 1) s += __shfl_down_sync(0xFFFFFFFFu, s, o);
        if (lane == 0) g_part[blockIdx.x] = s;
    }
}

// scan stage B: exclusive scan of block partials (single block)
__global__ void scanB_kernel(int nblocks, int n) {
    int tid = threadIdx.x, lane = tid & 31, wid = tid >> 5;
    __shared__ int ws[8];
    int v = (tid < nblocks) ? g_part[tid] : 0;
    int x = v;
    #pragma unroll
    for (int o = 1; o < 32; o <<= 1) {
        int y = __shfl_up_sync(0xFFFFFFFFu, x, o);
        if (lane >= o) x += y;
    }
    if (lane == 31) ws[wid] = x;
    __syncthreads();
    if (wid == 0) {
        int s = (lane < 8) ? ws[lane] : 0;
        #pragma unroll
        for (int o = 1; o < 8; o <<= 1) {
            int y = __shfl_up_sync(0xFFFFFFFFu, s, o);
            if (lane >= o) s += y;
        }
        ws[lane] = s;
    }
    __syncthreads();
    int incl = x + (wid > 0 ? ws[wid - 1] : 0);
    if (tid < nblocks) g_part[tid] = incl - v;       // exclusive
    if (tid == nblocks - 1) g_ptr[n] = incl;         // total
}

// scan stage C: intra-block exclusive scan + block offset -> g_ptr
__global__ void scanC_kernel(int n) {
    int i = blockIdx.x * blockDim.x + threadIdx.x;
    int lane = threadIdx.x & 31, wid = threadIdx.x >> 5;
    __shared__ int ws[SCAN_TPB / 32];
    int v = (i < n) ? (g_deg[i] - 1) : 0;
    int x = v;
    #pragma unroll
    for (int o = 1; o < 32; o <<= 1) {
        int y = __shfl_up_sync(0xFFFFFFFFu, x, o);
        if (lane >= o) x += y;
    }
    if (lane == 31) ws[wid] = x;
    __syncthreads();
    if (wid == 0) {
        int s = (lane < SCAN_TPB / 32) ? ws[lane] : 0;
        #pragma unroll
        for (int o = 1; o < SCAN_TPB / 32; o <<= 1) {
            int y = __shfl_up_sync(0xFFFFFFFFu, s, o);
            if (lane >= o) s += y;
        }
        ws[lane] = s;
    }
    __syncthreads();
    int incl = x + (wid > 0 ? ws[wid - 1] : 0);
    if (i < n) g_ptr[i] = incl - v + g_part[blockIdx.x];
}

__global__ void scatter_kernel(const int* __restrict__ ei, int E, int n) {
    int e = blockIdx.x * blockDim.x + threadIdx.x;
    if (e < E) {
        int r = clampN(ei[e], n);
        int c = clampN(ei[E + e], n);
        int pos = g_ptr[c] + atomicAdd(&g_cursor[c], 1);
        float w = g_dinv[r] * g_dinv[c];
        g_csr[pos] = make_int2(r, __float_as_int(w));
    }
}

// ---------------- MLP encode: warp/node, lane owns features (2l, 2l+1), f32x2 ----
__global__ void mlp1_kernel(const float* __restrict__ x,
                            const float* __restrict__ W1,
                            const float* __restrict__ b1, int n) {
    int warp = (blockIdx.x * blockDim.x + threadIdx.x) >> 5;
    int lane = threadIdx.x & 31;
    if (warp >= n) return;
    const float* xr = x + (size_t)warp * FIN;
    unsigned long long acc;
    PACK2(acc, b1[2 * lane], b1[2 * lane + 1]);
    for (int kb = 0; kb < FIN; kb += 32) {
        float xv = xr[kb + lane];
        #pragma unroll
        for (int j = 0; j < 32; j++) {
            float xk = __shfl_sync(0xFFFFFFFFu, xv, j);
            unsigned long long xk2, wv;
            PACK2(xk2, xk, xk);
            wv = *(const unsigned long long*)&W1[(kb + j) * FH + 2 * lane];
            FMA2(acc, xk2, wv, acc);
        }
    }
    float a0, a1;
    UNPACK2(a0, a1, acc);
    *(float2*)&g_mlp1[warp * FH + 2 * lane] =
        make_float2(fmaxf(a0, 0.0f), fmaxf(a1, 0.0f));
}

__global__ void mlp2_kernel(const float* __restrict__ W2,
                            const float* __restrict__ b2, int n) {
    int warp = (blockIdx.x * blockDim.x + threadIdx.x) >> 5;
    int lane = threadIdx.x & 31;
    if (warp >= n) return;
    const float* hr = g_mlp1 + warp * FH;
    unsigned long long acc;
    PACK2(acc, b2[2 * lane], b2[2 * lane + 1]);
    #pragma unroll
    for (int kb = 0; kb < FH; kb += 32) {
        float hv = hr[kb + lane];
        #pragma unroll
        for (int j = 0; j < 32; j++) {
            float hk = __shfl_sync(0xFFFFFFFFu, hv, j);
            unsigned long long hk2, wv;
            PACK2(hk2, hk, hk);
            wv = *(const unsigned long long*)&W2[(kb + j) * FH + 2 * lane];
            FMA2(acc, hk2, wv, acc);
        }
    }
    float a0, a1;
    UNPACK2(a0, a1, acc);
    g_hA[warp * 32 + lane] = __floats2half2_rn(a0, a1);   // features (2l, 2l+1)
    g_h0[warp * 32 + lane] = make_float2(a0, a1);
}

// ---------------- APPNP step: warp/node, uniform CSR loads, unroll x4 ----------
template <int SRC_A>
__global__ void prop_kernel(int n) {
    int node = (blockIdx.x * blockDim.x + threadIdx.x) >> 5;
    int lane = threadIdx.x & 31;
    if (node >= n) return;
    const __half2* __restrict__ hin  = SRC_A ? g_hA : g_hB;
    __half2*       __restrict__ hout = SRC_A ? g_hB : g_hA;

    int start = g_ptr[node];
    int end   = g_ptr[node + 1];

    float di = g_dinv[node];
    float wself = di * di;
    float2 hv = __half22float2(hin[node * 32 + lane]);
    float ax = wself * hv.x;
    float ay = wself * hv.y;

    int e = start;
    for (; e + 4 <= end; e += 4) {
        int2 s0 = g_csr[e + 0];          // uniform (broadcast) loads
        int2 s1 = g_csr[e + 1];
        int2 s2 = g_csr[e + 2];
        int2 s3 = g_csr[e + 3];
        __half2 v0 = hin[s0.x * 32 + lane];  // 4 independent gathers in flight
        __half2 v1 = hin[s1.x * 32 + lane];
        __half2 v2 = hin[s2.x * 32 + lane];
        __half2 v3 = hin[s3.x * 32 + lane];
        float2 f0 = __half22float2(v0);
        float2 f1 = __half22float2(v1);
        float2 f2 = __half22float2(v2);
        float2 f3 = __half22float2(v3);
        float w0 = __int_as_float(s0.y);
        float w1 = __int_as_float(s1.y);
        float w2 = __int_as_float(s2.y);
        float w3 = __int_as_float(s3.y);
        ax = fmaf(w0, f0.x, ax);  ay = fmaf(w0, f0.y, ay);
        ax = fmaf(w1, f1.x, ax);  ay = fmaf(w1, f1.y, ay);
        ax = fmaf(w2, f2.x, ax);  ay = fmaf(w2, f2.y, ay);
        ax = fmaf(w3, f3.x, ax);  ay = fmaf(w3, f3.y, ay);
    }
    for (; e < end; e++) {
        int2 s = g_csr[e];
        float2 f = __half22float2(hin[s.x * 32 + lane]);
        float w = __int_as_float(s.y);
        ax = fmaf(w, f.x, ax);
        ay = fmaf(w, f.y, ay);
    }

    float2 t = g_h0[node * 32 + lane];
    hout[node * 32 + lane] =
        __floats2half2_rn(0.9f * ax + 0.1f * t.x, 0.9f * ay + 0.1f * t.y);
}

// ---------------- decode: out = h @ Wf + bf (pairing-aware) ----------------
__global__ void decode_kernel(const float* __restrict__ Wf,
                              const float* __restrict__ bf,
                              float* __restrict__ out, int n) {
    int warp = (blockIdx.x * blockDim.x + threadIdx.x) >> 5;
    int lane = threadIdx.x & 31;
    if (warp >= n) return;
    unsigned int hbits = *(const unsigned int*)&g_hA[warp * 32 + lane]; // feats (2l,2l+1)
    float acc0 = bf[lane];
    float acc1 = (lane < FOUT - 32) ? bf[lane + 32] : 0.0f;
    #pragma unroll
    for (int j = 0; j < 32; j++) {
        unsigned int hb = __shfl_sync(0xFFFFFFFFu, hbits, j);
        __half2 hh = *(__half2*)&hb;
        float2 hf = __half22float2(hh);     // features (2j, 2j+1)
        acc0 = fmaf(hf.x, Wf[(2 * j) * FOUT + lane], acc0);
        acc0 = fmaf(hf.y, Wf[(2 * j + 1) * FOUT + lane], acc0);
        if (lane < FOUT - 32) {
            acc1 = fmaf(hf.x, Wf[(2 * j) * FOUT + lane + 32], acc1);
            acc1 = fmaf(hf.y, Wf[(2 * j + 1) * FOUT + lane + 32], acc1);
        }
    }
    out[(size_t)warp * FOUT + lane] = acc0;
    if (lane < FOUT - 32)
        out[(size_t)warp * FOUT + lane + 32] = acc1;
}

// ---------------- launch ----------------
extern "C" void kernel_launch(void* const* d_in, const int* in_sizes, int n_in,
                              void* d_out, int out_size) {
    const float* x  = (const float*)d_in[0];
    const int*   ei = (const int*)d_in[1];
    const float* W1 = (const float*)d_in[2];
    const float* b1 = (const float*)d_in[3];
    const float* W2 = (const float*)d_in[4];
    const float* b2 = (const float*)d_in[5];
    const float* Wf = (const float*)d_in[6];
    const float* bf = (const float*)d_in[7];

    int N = in_sizes[0] / FIN;
    int E = in_sizes[1] / 2;
    if (N > MAXN) N = MAXN;
    if (E > MAXE) E = MAXE;

    int tpb = 256;
    int nblk = (N + SCAN_TPB - 1) / SCAN_TPB;

    init_kernel<<<(N + tpb - 1) / tpb, tpb>>>(N);
    hist_kernel<<<(E + tpb - 1) / tpb, tpb>>>(ei, E, N);
    dinv_kernel<<<(N + tpb - 1) / tpb, tpb>>>(N);
    scanA_kernel<<<nblk, SCAN_TPB>>>(N);
    scanB_kernel<<<1, MAXBLK>>>(nblk, N);
    scanC_kernel<<<nblk, SCAN_TPB>>>(N);
    scatter_kernel<<<(E + tpb - 1) / tpb, tpb>>>(ei, E, N);

    int wblocks = (N + 7) / 8;                 // 8 warps / 256-thread block
    mlp1_kernel<<<wblocks, tpb>>>(x, W1, b1, N);
    mlp2_kernel<<<wblocks, tpb>>>(W2, b2, N);

    for (int t = 0; t < KSTEPS; t++) {
        if ((t & 1) == 0) prop_kernel<1><<<wblocks, tpb>>>(N);
        else              prop_kernel<0><<<wblocks, tpb>>>(N);
    }
    decode_kernel<<<wblocks, tpb>>>(Wf, bf, (float*)d_out, N);
}